// round 15
// baseline (speedup 1.0000x reference)
#include <cuda_runtime.h>
#include <math.h>

#define NB 64
#define NG 32
#define TOT 64512          // 49152 + 12288 + 3072
#define NTASK 192          // 64 images x 3 scales
#define PB 2048            // positive-key histogram bins (bits>>20 for xo>=0)
#define HB 4096            // refine histogram bins
#define MAXN 49152
#define SH_CAP 4096        // shared tie-buffer capacity
#define STG_CAP 1536       // 512 threads x 3 anchors

__device__ double   g_acc;                 // reset by last k_select block
__device__ unsigned g_done;                // reset by last k_select block
__device__ int      g_numpos[NTASK];       // zeroed by k_select after read
__device__ int      g_pcnt[NTASK];         // A-partition sizes, zeroed by k_select
__device__ int      g_ncnt[NTASK];         // B-partition sizes, zeroed by k_select
__device__ float    g_keys[(size_t)NB * TOT];
__device__ unsigned g_hist[NTASK * PB];    // zeroed by k_select after read
__device__ unsigned g_buf[(size_t)NTASK * MAXN];  // tie overflow

__device__ __forceinline__ float sl1(float x) {
    float ax = fabsf(x);
    return (ax < 1.0f) ? 0.5f * x * x : ax - 0.5f;
}
__device__ __forceinline__ float softplus0(float x) {
    return fmaxf(x, 0.0f) + log1pf(expf(-fabsf(x)));
}
// float -> order-preserving key (descending float == descending uint)
__device__ __forceinline__ unsigned f2u(float f) {
    unsigned u = __float_as_uint(f);
    return (u & 0x80000000u) ? ~u : (u | 0x80000000u);
}
__device__ __forceinline__ float key2f(unsigned k) {
    unsigned u = (k & 0x80000000u) ? (k & 0x7FFFFFFFu) : ~k;
    return __uint_as_float(u);
}

// exclusive prefix over 1024 threads (warp shuffles)
__device__ __forceinline__ int scan1024(int v) {
    __shared__ int wsum[32];
    const int lane = threadIdx.x & 31, wid = threadIdx.x >> 5;
    int inc = v;
    #pragma unroll
    for (int o = 1; o < 32; o <<= 1) {
        int t = __shfl_up_sync(0xFFFFFFFFu, inc, o);
        if (lane >= o) inc += t;
    }
    __syncthreads();               // protect wsum reuse across calls
    if (lane == 31) wsum[wid] = inc;
    __syncthreads();
    if (wid == 0) {
        int w = wsum[lane];
        int winc = w;
        #pragma unroll
        for (int o = 1; o < 32; o <<= 1) {
            int t = __shfl_up_sync(0xFFFFFFFFu, winc, o);
            if (lane >= o) winc += t;
        }
        wsum[lane] = winc - w;     // exclusive warp offsets
    }
    __syncthreads();
    return wsum[wid] + inc - v;
}

// ---------------------------------------------------------------------------
// Pass 1: 32x16-pixel tiles (512 thr), per-warp GT culling, losses,
// positive-only histogram, PARTITIONED key compaction:
//   A (neg & xo>=0) -> front of task region, B (neg & xo<0) -> back.
// Non-neg anchors are dropped (their sentinels contribute 0 in all branches).
// ---------------------------------------------------------------------------
__global__ __launch_bounds__(512) void k_assign(
    const float* __restrict__ pred0,
    const float* __restrict__ pred1,
    const float* __restrict__ pred2,
    const float* __restrict__ gt_boxes,
    const int*   __restrict__ gt_labels)
{
    const int b   = blockIdx.y;
    const int cx_ = blockIdx.x;            // 0..41
    const int tid = threadIdx.x;
    const int lane = tid & 31, wid = tid >> 5;

    int scale, blkbase, W, HW, keyoff, TW;
    float stride;
    const float* pred;
    if (cx_ < 32)      { scale = 0; blkbase = 0;  W = 128; HW = 16384; stride = 8.0f;  keyoff = 0;     pred = pred0; TW = 4; }
    else if (cx_ < 40) { scale = 1; blkbase = 32; W = 64;  HW = 4096;  stride = 16.0f; keyoff = 49152; pred = pred1; TW = 2; }
    else               { scale = 2; blkbase = 40; W = 32;  HW = 1024;  stride = 32.0f; keyoff = 61440; pred = pred2; TW = 1; }

    const int tile = cx_ - blkbase;
    const int tbx = tile % TW, tby = tile / TW;   // 32-wide x 16-tall tiles
    const int w = tbx * 32 + lane;                // warp = one pixel row
    const int h = tby * 16 + wid;
    const int p = h * W + w;
    const int task = b * 3 + scale;
    const int NN = 3 * HW;

    __shared__ float4   s_wbox[16 * NG];
    __shared__ float    s_warea[16 * NG];
    __shared__ int      s_wlbl[16 * NG];
    __shared__ unsigned sh_hist[PB];
    __shared__ unsigned stA[STG_CAP];
    __shared__ unsigned stB[STG_CAP];
    __shared__ int      s_cA, s_cB, s_bA, s_bB;
    __shared__ float    rs[16];
    __shared__ int      rc[16];

    for (int i = tid; i < PB; i += 512) sh_hist[i] = 0;
    if (tid == 0) { s_cA = 0; s_cB = 0; }

    // Per-warp cull: this warp's row reach is exactly the min/max anchor
    // extents of its 32 pixels (largest anchor half-size = 2.5*stride).
    // Culled GTs have inter==0 with every anchor this warp evaluates.
    int cnt;
    {
        float4 g = ((const float4*)gt_boxes)[b * NG + lane];
        int   lb = gt_labels[b * NG + lane];
        float rx0 = ((float)(tbx * 32) - 2.0f) * stride;
        float rx1 = ((float)(tbx * 32) + 34.0f) * stride;
        float ry0 = ((float)(h - 2)) * stride;
        float ry1 = ((float)(h + 3)) * stride;
        bool c = (g.x <= rx1) && (g.z >= rx0) && (g.y <= ry1) && (g.w >= ry0);
        unsigned m = __ballot_sync(0xFFFFFFFFu, c);
        cnt = __popc(m);
        if (c) {
            int pos = __popc(m & ((1u << lane) - 1u));
            s_wbox[wid * NG + pos]  = g;
            s_warea[wid * NG + pos] = (g.z - g.x) * (g.w - g.y);
            s_wlbl[wid * NG + pos]  = lb;
        }
        __syncwarp();
    }
    __syncthreads();               // hist zero + counters init complete

    float loss = 0.0f;
    int   cpos = 0;
    const float cxp = (w + 0.5f) * stride;
    const float cyp = (h + 0.5f) * stride;
    const float4* wbox  = s_wbox  + wid * NG;
    const float*  warea = s_warea + wid * NG;
    const int*    wlbl  = s_wlbl  + wid * NG;

    #pragma unroll
    for (int a = 0; a < 3; ++a) {
        const float s   = (float)(3 + a) * stride;
        const float hlf = 0.5f * s;
        const float ax1 = cxp - hlf, ay1 = cyp - hlf;
        const float ax2 = cxp + hlf, ay2 = cyp + hlf;
        const float areaA = s * s;

        // division-free argmax over surviving GTs (first-max tie-break preserved)
        float BI = 0.0f, BS = 1.0f; int BX = 0;
        for (int j = 0; j < cnt; ++j) {       // cnt is warp-uniform
            float4 g = wbox[j];
            float lx = fmaxf(ax1, g.x), ly = fmaxf(ay1, g.y);
            float rx = fminf(ax2, g.z), ry = fminf(ay2, g.w);
            float iw = fmaxf(rx - lx, 0.0f), ih = fmaxf(ry - ly, 0.0f);
            float inter = iw * ih;
            float S     = areaA + warea[j];
            if (inter * BS > BI * S) { BI = inter; BS = S; BX = j; }
        }

        const float denom    = (BS - BI) + 1e-9f;
        const float best_iou = BI / denom;
        const bool  pos = (best_iou >= 0.5f);
        const bool  neg = (best_iou <  0.4f);

        const size_t base = ((size_t)b * 24 + a * 8) * (size_t)HW + p;
        const float  xo   = pred[base + 4 * (size_t)HW];

        // partitioned staging (warp-aggregated shared-counter compaction)
        {
            const unsigned bits = __float_as_uint(xo);
            const bool isA = neg && (xo >= 0.0f);
            const bool isB = neg && !(xo >= 0.0f);
            unsigned mA = __ballot_sync(0xFFFFFFFFu, isA);
            unsigned mB = __ballot_sync(0xFFFFFFFFu, isB);
            int ldA = __ffs(mA) - 1, ldB = __ffs(mB) - 1;
            int bA = 0, bB = 0;
            if (lane == ldA) bA = atomicAdd(&s_cA, __popc(mA));
            if (lane == ldB) bB = atomicAdd(&s_cB, __popc(mB));
            bA = __shfl_sync(0xFFFFFFFFu, bA, ldA & 31);
            bB = __shfl_sync(0xFFFFFFFFu, bB, ldB & 31);
            if (isA) {
                stA[bA + __popc(mA & ((1u << lane) - 1u))] = bits;
                // For xo>=0: f2u(xo)>>20 == (bits>>20)+2048, so bin = bits>>20.
                atomicAdd(&sh_hist[bits >> 20], 1u);
            }
            if (isB) stB[bB + __popc(mB & ((1u << lane) - 1u))] = bits;
        }

        if (pos) {
            cpos++;
            loss += fmaxf(xo, 0.0f) - xo + log1pf(expf(-fabsf(xo)));

            float4 g = wbox[BX];
            float gx = (g.x + g.z) * 0.5f;
            float gy = (g.y + g.w) * 0.5f;
            float gw = fmaxf(g.z - g.x, 1e-6f);
            float gh = fmaxf(g.w - g.y, 1e-6f);
            float aw = fmaxf(ax2 - ax1, 1e-6f);
            float ah = fmaxf(ay2 - ay1, 1e-6f);

            float ttx = (gx - cxp) / aw;
            float tty = (gy - cyp) / ah;
            float ttw = logf(gw / aw);
            float tth = logf(gh / ah);

            float p0 = pred[base];
            float p1 = pred[base + 1 * (size_t)HW];
            float p2 = pred[base + 2 * (size_t)HW];
            float p3 = pred[base + 3 * (size_t)HW];
            loss += sl1(p0 - ttx) + sl1(p1 - tty) + sl1(p2 - ttw) + sl1(p3 - tth);

            float c0 = pred[base + 5 * (size_t)HW];
            float c1 = pred[base + 6 * (size_t)HW];
            float c2 = pred[base + 7 * (size_t)HW];
            float m  = fmaxf(c0, fmaxf(c1, c2));
            float lse = m + logf(expf(c0 - m) + expf(c1 - m) + expf(c2 - m));
            int   t   = max(wlbl[BX], 0);
            float pt  = (t == 0) ? c0 : ((t == 1) ? c1 : c2);
            loss += lse - pt;
        }
    }

    #pragma unroll
    for (int o = 16; o; o >>= 1) {
        loss += __shfl_down_sync(0xFFFFFFFFu, loss, o);
        cpos += __shfl_down_sync(0xFFFFFFFFu, cpos, o);
    }
    if (lane == 0) { rs[wid] = loss; rc[wid] = cpos; }
    __syncthreads();               // staging + reductions complete
    if (tid == 0) {
        float L = 0.0f; int C = 0;
        #pragma unroll
        for (int i = 0; i < 16; ++i) { L += rs[i]; C += rc[i]; }
        if (L != 0.0f) atomicAdd(&g_acc, (double)L);
        if (C)         atomicAdd(&g_numpos[task], C);
        s_bA = atomicAdd(&g_pcnt[task], s_cA);
        s_bB = atomicAdd(&g_ncnt[task], s_cB);
    }
    __syncthreads();

    // coalesced flush: A from front, B from back of the task region
    float* regn = g_keys + (size_t)b * TOT + keyoff;
    const int cA = s_cA, cB = s_cB;
    for (int i = tid; i < cA; i += 512) regn[s_bA + i] = __uint_as_float(stA[i]);
    for (int i = tid; i < cB; i += 512) regn[NN - s_bB - cB + i] = __uint_as_float(stB[i]);

    unsigned* gh = g_hist + task * PB;
    for (int i = tid; i < PB; i += 512) {
        unsigned c = sh_hist[i];
        if (c) atomicAdd(&gh[i], c);
    }
}

// ---------------------------------------------------------------------------
// Fused select + finalize, one block per task (1024 threads).
// Phase A: descending scan of positive-key histogram -> top-12 threshold + kk.
// Phase B: scan A partition only (common); fallback adds B partition:
//   k >= |A|+|B|  -> sum everything (reference selects all negs)
//   else          -> B keys become the tie set for generic 3-level refine.
// Last-finished block writes the output and resets accumulators.
// ---------------------------------------------------------------------------
__global__ __launch_bounds__(1024) void k_select(float* out) {
    __shared__ unsigned s_tie[SH_CAP];
    __shared__ unsigned h2[HB];
    __shared__ unsigned h3[256];
    __shared__ int      s_tiecnt;
    __shared__ int      sT, sKK, sSum, sQ, sT2, sKK2, sT3, sKK3;
    __shared__ float    rs[32];

    const int task = blockIdx.x;
    const int s = task % 3, b = task / 3;
    const int N   = (s == 0) ? 49152 : ((s == 1) ? 12288 : 3072);
    const int off = (s == 0) ? 0     : ((s == 1) ? 49152 : 61440);
    const int tid = threadIdx.x;

    for (int i = tid; i < HB; i += 1024) h2[i] = 0;
    if (tid < 256) h3[tid] = 0;
    if (tid == 0) { s_tiecnt = 0; sT = 0; sKK = 1; sT2 = 0; sKK2 = 1; sT3 = 0; sKK3 = 0; }

    int np = g_numpos[task];
    int k = 3 * max(1, np);
    if (k > N) k = N;

    // --- Phase A: plan over positive-key histogram (2 bins/thread, desc) ---
    unsigned* gh = g_hist + task * PB;
    {
        int cnt[2], tot = 0;
        #pragma unroll
        for (int i = 0; i < 2; ++i) {
            int bin = PB - 1 - (tid * 2 + i);
            cnt[i] = (int)gh[bin];
            gh[bin] = 0;                   // restore zero
            tot += cnt[i];
        }
        int excl = scan1024(tot);
        if (excl < k && excl + tot >= k) {
            int cum = excl;
            #pragma unroll
            for (int i = 0; i < 2; ++i) {
                if (cum + cnt[i] >= k) { sT = PB - 1 - (tid * 2 + i); sKK = k - cum; break; }
                cum += cnt[i];
            }
        }
        if (tid == 1023) sSum = excl + tot;   // |A| = total positive keys
    }
    if (tid == 0) {
        g_numpos[task] = 0;
        sQ = g_ncnt[task];
        g_ncnt[task] = 0;
        g_pcnt[task] = 0;
    }
    __syncthreads();
    const int Sall = sSum;                    // |A|
    const int Q    = sQ;                      // |B|
    const bool fb  = (k > Sall);
    const int kkB  = k - Sall;
    const bool norefine = fb && (kkB >= Q);   // select ALL negs
    unsigned T0 = 0;
    int kk = 1;
    if (!fb) { T0 = (unsigned)sT + 2048u; kk = sKK; }

    const float* keys = g_keys + (size_t)b * TOT + off;
    unsigned* obuf = g_buf + (size_t)task * MAXN;

    // --- Phase B: scan A partition [0, Sall) ---
    float local = 0.0f;
    for (int base = 0; base < Sall; base += 4096) {
        float v[4]; bool ok[4];
        #pragma unroll
        for (int q = 0; q < 4; ++q) {
            int i = base + tid + q * 1024;
            ok[q] = (i < Sall);
            if (ok[q]) v[q] = keys[i];
        }
        #pragma unroll
        for (int q = 0; q < 4; ++q) {
            if (!ok[q]) continue;
            float x = v[q];
            if (fb) { local += softplus0(x); continue; }
            unsigned u = f2u(x);
            unsigned bin = u >> 20;
            if (bin > T0) local += softplus0(x);
            else if (bin == T0) {
                int idx = atomicAdd(&s_tiecnt, 1);
                if (idx < SH_CAP) s_tie[idx] = u;
                else              obuf[idx - SH_CAP] = u;
            }
        }
    }
    // --- B partition [N-Q, N) only in fallback ---
    if (fb) {
        const float* keysB = keys + (N - Q);
        for (int base = 0; base < Q; base += 4096) {
            float v[4]; bool ok[4];
            #pragma unroll
            for (int q = 0; q < 4; ++q) {
                int i = base + tid + q * 1024;
                ok[q] = (i < Q);
                if (ok[q]) v[q] = keysB[i];
            }
            #pragma unroll
            for (int q = 0; q < 4; ++q) {
                if (!ok[q]) continue;
                float x = v[q];
                if (norefine) { local += softplus0(x); continue; }
                unsigned u = f2u(x);
                int idx = atomicAdd(&s_tiecnt, 1);
                if (idx < SH_CAP) s_tie[idx] = u;
                else              obuf[idx - SH_CAP] = u;
            }
        }
        kk = norefine ? 1 : kkB;
    }
    __syncthreads();
    const int m = s_tiecnt;

    // --- fallback level 0: select top-12 bin among tie members (B keys) ---
    if (fb && !norefine) {
        for (int i = tid; i < m; i += 1024) {
            unsigned u = (i < SH_CAP) ? s_tie[i] : obuf[i - SH_CAP];
            atomicAdd(&h2[u >> 20], 1u);
        }
        __syncthreads();
        {
            int c0[4], t0 = 0;
            #pragma unroll
            for (int i = 0; i < 4; ++i) {
                int bin = HB - 1 - (tid * 4 + i);
                c0[i] = (int)h2[bin];
                t0 += c0[i];
            }
            int ex = scan1024(t0);
            if (ex < kk && ex + t0 >= kk) {
                int cum = ex;
                #pragma unroll
                for (int i = 0; i < 4; ++i) {
                    if (cum + c0[i] >= kk) { sT2 = HB - 1 - (tid * 4 + i); sKK2 = kk - cum; break; }
                    cum += c0[i];
                }
            }
        }
        __syncthreads();
        T0 = (unsigned)sT2;
        kk = sKK2;
        for (int i = tid; i < HB; i += 1024) h2[i] = 0;   // re-zero for C1
        __syncthreads();
    }

    // --- Phase C1: sum tops>T0 (fb only), mid-12 histogram of top==T0 ---
    for (int i = tid; i < m; i += 1024) {
        unsigned u = (i < SH_CAP) ? s_tie[i] : obuf[i - SH_CAP];
        unsigned top = u >> 20;
        if (top > T0)       local += softplus0(key2f(u));
        else if (top == T0) atomicAdd(&h2[(u >> 8) & 0xFFFu], 1u);
    }
    __syncthreads();
    {
        int c2[4], t2 = 0;
        #pragma unroll
        for (int i = 0; i < 4; ++i) {
            int bin = HB - 1 - (tid * 4 + i);
            c2[i] = (int)h2[bin];
            t2 += c2[i];
        }
        int ex = scan1024(t2);
        if (ex < kk && ex + t2 >= kk) {
            int cum = ex;
            #pragma unroll
            for (int i = 0; i < 4; ++i) {
                if (cum + c2[i] >= kk) { sT2 = HB - 1 - (tid * 4 + i); sKK2 = kk - cum; break; }
                cum += c2[i];
            }
        }
    }
    __syncthreads();
    const unsigned T2 = (unsigned)sT2;
    const int kk2 = sKK2;

    // --- Phase C2: sum mid>T2; low-byte histogram for mid==T2 ---
    for (int i = tid; i < m; i += 1024) {
        unsigned u = (i < SH_CAP) ? s_tie[i] : obuf[i - SH_CAP];
        if ((u >> 20) != T0) continue;
        unsigned mid = (u >> 8) & 0xFFFu;
        if (mid > T2)       local += softplus0(key2f(u));
        else if (mid == T2) atomicAdd(&h3[u & 0xFFu], 1u);
    }
    __syncthreads();
    {
        int c3 = (tid < 256) ? (int)h3[255 - tid] : 0;
        int ex = scan1024(c3);
        if (tid < 256 && ex < kk2 && ex + c3 >= kk2) { sT3 = 255 - tid; sKK3 = kk2 - ex; }
    }
    __syncthreads();
    const unsigned T3 = (unsigned)sT3;
    const int kk3 = sKK3;
    const unsigned ustar = (T0 << 20) | (T2 << 8) | T3;

    // --- Phase C3: top==T0 && mid==T2 && low>T3 ---
    for (int i = tid; i < m; i += 1024) {
        unsigned u = (i < SH_CAP) ? s_tie[i] : obuf[i - SH_CAP];
        if ((u >> 20) == T0 && ((u >> 8) & 0xFFFu) == T2 && (u & 0xFFu) > T3)
            local += softplus0(key2f(u));
    }

    // block reduction (32 warps)
    #pragma unroll
    for (int o = 16; o; o >>= 1) local += __shfl_down_sync(0xFFFFFFFFu, local, o);
    const int wid = tid >> 5, lane = tid & 31;
    if (lane == 0) rs[wid] = local;
    __syncthreads();
    if (tid == 0) {
        float tot2 = 0.0f;
        #pragma unroll
        for (int i = 0; i < 32; ++i) tot2 += rs[i];
        if (!norefine) tot2 += (float)kk3 * softplus0(key2f(ustar));
        atomicAdd(&g_acc, (double)tot2);

        // finalize: last-finished block writes the output
        __threadfence();
        unsigned d = atomicAdd(&g_done, 1u);
        if (d == NTASK - 1) {
            unsigned long long bits =
                atomicAdd((unsigned long long*)&g_acc, 0ULL);   // coherent read
            out[0] = (float)(__longlong_as_double(bits) * (1.0 / 64.0));
            atomicExch((unsigned long long*)&g_acc, 0ULL);       // reset
            atomicExch(&g_done, 0u);                             // reset
        }
    }
}

extern "C" void kernel_launch(void* const* d_in, const int* in_sizes, int n_in,
                              void* d_out, int out_size)
{
    const float* pred0 = (const float*)d_in[0];
    const float* pred1 = (const float*)d_in[2];
    const float* pred2 = (const float*)d_in[4];
    const float* gtb   = (const float*)d_in[6];
    const int*   gtl   = (const int*)d_in[7];

    dim3 ga(42, NB);
    k_assign<<<ga, 512>>>(pred0, pred1, pred2, gtb, gtl);
    k_select<<<NTASK, 1024>>>((float*)d_out);
}

// round 16
// speedup vs baseline: 1.4407x; 1.4407x over previous
#include <cuda_runtime.h>
#include <math.h>

#define NB 64
#define NG 32
#define TOT 64512          // 49152 + 12288 + 3072
#define NTASK 192          // 64 images x 3 scales
#define PB 2048            // positive-key histogram bins (bits>>20 for xo>=0)
#define HB 4096            // refine histogram bins
#define MAXN 49152
#define SH_CAP 4096        // shared tie-buffer capacity

__device__ double   g_acc;                 // reset by last k_select block
__device__ unsigned g_done;                // reset by last k_select block
__device__ int      g_numpos[NTASK];       // zeroed by k_select after read
__device__ float    g_keys[(size_t)NB * TOT];
__device__ unsigned g_hist[NTASK * PB];    // zeroed by k_select after read
__device__ unsigned g_buf[(size_t)NTASK * MAXN];  // tie overflow

__device__ __forceinline__ float sl1(float x) {
    float ax = fabsf(x);
    return (ax < 1.0f) ? 0.5f * x * x : ax - 0.5f;
}
__device__ __forceinline__ float softplus0(float x) {
    return fmaxf(x, 0.0f) + log1pf(expf(-fabsf(x)));
}
// float -> order-preserving key (descending float == descending uint)
__device__ __forceinline__ unsigned f2u(float f) {
    unsigned u = __float_as_uint(f);
    return (u & 0x80000000u) ? ~u : (u | 0x80000000u);
}
__device__ __forceinline__ float key2f(unsigned k) {
    unsigned u = (k & 0x80000000u) ? (k & 0x7FFFFFFFu) : ~k;
    return __uint_as_float(u);
}

// exclusive prefix over 1024 threads (warp shuffles)
__device__ __forceinline__ int scan1024(int v) {
    __shared__ int wsum[32];
    const int lane = threadIdx.x & 31, wid = threadIdx.x >> 5;
    int inc = v;
    #pragma unroll
    for (int o = 1; o < 32; o <<= 1) {
        int t = __shfl_up_sync(0xFFFFFFFFu, inc, o);
        if (lane >= o) inc += t;
    }
    __syncthreads();               // protect wsum reuse across calls
    if (lane == 31) wsum[wid] = inc;
    __syncthreads();
    if (wid == 0) {
        int w = wsum[lane];
        int winc = w;
        #pragma unroll
        for (int o = 1; o < 32; o <<= 1) {
            int t = __shfl_up_sync(0xFFFFFFFFu, winc, o);
            if (lane >= o) winc += t;
        }
        wsum[lane] = winc - w;     // exclusive warp offsets
    }
    __syncthreads();
    return wsum[wid] + inc - v;
}

// ---------------------------------------------------------------------------
// Pass 1: 32x16-pixel tiles (512 thr), PER-WARP (per-row) GT culling,
// anchor-outer/GT-inner argmax, losses, positive-only histogram, key scatter.
// ---------------------------------------------------------------------------
__global__ __launch_bounds__(512) void k_assign(
    const float* __restrict__ pred0,
    const float* __restrict__ pred1,
    const float* __restrict__ pred2,
    const float* __restrict__ gt_boxes,
    const int*   __restrict__ gt_labels)
{
    const int b   = blockIdx.y;
    const int cx_ = blockIdx.x;            // 0..41
    const int tid = threadIdx.x;
    const int lane = tid & 31, wid = tid >> 5;

    int scale, blkbase, W, HW, keyoff, TW;
    float stride;
    const float* pred;
    if (cx_ < 32)      { scale = 0; blkbase = 0;  W = 128; HW = 16384; stride = 8.0f;  keyoff = 0;     pred = pred0; TW = 4; }
    else if (cx_ < 40) { scale = 1; blkbase = 32; W = 64;  HW = 4096;  stride = 16.0f; keyoff = 49152; pred = pred1; TW = 2; }
    else               { scale = 2; blkbase = 40; W = 32;  HW = 1024;  stride = 32.0f; keyoff = 61440; pred = pred2; TW = 1; }

    const int tile = cx_ - blkbase;
    const int tbx = tile % TW, tby = tile / TW;   // 32-wide x 16-tall tiles
    const int w = tbx * 32 + lane;                // warp = one pixel row
    const int h = tby * 16 + wid;
    const int p = h * W + w;

    __shared__ float4   s_wbox[16 * NG];
    __shared__ float    s_warea[16 * NG];
    __shared__ int      s_wlbl[16 * NG];
    __shared__ unsigned sh_hist[PB];
    __shared__ float    rs[16];
    __shared__ int      rc[16];

    for (int i = tid; i < PB; i += 512) sh_hist[i] = 0;

    // Per-warp cull: this warp's row reach is exactly the min/max anchor
    // extents of its 32 pixels (largest anchor half-size = 2.5*stride).
    // Culled GTs have inter==0 with every anchor this warp evaluates, so
    // they can never win the argmax; all-zero IoU => neg, best_idx unused.
    int cnt;
    {
        float4 g = ((const float4*)gt_boxes)[b * NG + lane];
        int   lb = gt_labels[b * NG + lane];
        float rx0 = ((float)(tbx * 32) - 2.0f) * stride;
        float rx1 = ((float)(tbx * 32) + 34.0f) * stride;
        float ry0 = ((float)(h - 2)) * stride;
        float ry1 = ((float)(h + 3)) * stride;
        bool c = (g.x <= rx1) && (g.z >= rx0) && (g.y <= ry1) && (g.w >= ry0);
        unsigned m = __ballot_sync(0xFFFFFFFFu, c);
        cnt = __popc(m);
        if (c) {
            int pos = __popc(m & ((1u << lane) - 1u));
            s_wbox[wid * NG + pos]  = g;
            s_warea[wid * NG + pos] = (g.z - g.x) * (g.w - g.y);
            s_wlbl[wid * NG + pos]  = lb;
        }
        __syncwarp();
    }
    __syncthreads();               // hist zeroing complete before atomics

    float loss = 0.0f;
    int   cpos = 0;
    const float cxp = (w + 0.5f) * stride;
    const float cyp = (h + 0.5f) * stride;
    float* keyb = g_keys + (size_t)b * TOT + keyoff;
    const float4* wbox  = s_wbox  + wid * NG;
    const float*  warea = s_warea + wid * NG;
    const int*    wlbl  = s_wlbl  + wid * NG;

    #pragma unroll
    for (int a = 0; a < 3; ++a) {
        const float s   = (float)(3 + a) * stride;
        const float hlf = 0.5f * s;
        const float ax1 = cxp - hlf, ay1 = cyp - hlf;
        const float ax2 = cxp + hlf, ay2 = cyp + hlf;
        const float areaA = s * s;

        // division-free argmax over surviving GTs (first-max tie-break preserved)
        float BI = 0.0f, BS = 1.0f; int BX = 0;
        for (int j = 0; j < cnt; ++j) {       // cnt is warp-uniform
            float4 g = wbox[j];
            float lx = fmaxf(ax1, g.x), ly = fmaxf(ay1, g.y);
            float rx = fminf(ax2, g.z), ry = fminf(ay2, g.w);
            float iw = fmaxf(rx - lx, 0.0f), ih = fmaxf(ry - ly, 0.0f);
            float inter = iw * ih;
            float S     = areaA + warea[j];
            if (inter * BS > BI * S) { BI = inter; BS = S; BX = j; }
        }

        const float denom    = (BS - BI) + 1e-9f;
        const float best_iou = BI / denom;
        const bool  pos = (best_iou >= 0.5f);
        const bool  neg = (best_iou <  0.4f);

        const size_t base = ((size_t)b * 24 + a * 8) * (size_t)HW + p;
        const float  xo   = pred[base + 4 * (size_t)HW];
        const float  key  = neg ? xo : -1e30f;
        keyb[a * HW + p] = key;

        // positive-only histogram: neg keys with xo >= +0.0.
        // For xo >= 0, f2u(xo)>>20 == (bits>>20) + 2048, so bin = bits>>20.
        if (neg && xo >= 0.0f)
            atomicAdd(&sh_hist[__float_as_uint(xo) >> 20], 1u);

        if (pos) {
            cpos++;
            loss += fmaxf(xo, 0.0f) - xo + log1pf(expf(-fabsf(xo)));

            float4 g = wbox[BX];
            float gx = (g.x + g.z) * 0.5f;
            float gy = (g.y + g.w) * 0.5f;
            float gw = fmaxf(g.z - g.x, 1e-6f);
            float gh = fmaxf(g.w - g.y, 1e-6f);
            float aw = fmaxf(ax2 - ax1, 1e-6f);
            float ah = fmaxf(ay2 - ay1, 1e-6f);

            float ttx = (gx - cxp) / aw;
            float tty = (gy - cyp) / ah;
            float ttw = logf(gw / aw);
            float tth = logf(gh / ah);

            float p0 = pred[base];
            float p1 = pred[base + 1 * (size_t)HW];
            float p2 = pred[base + 2 * (size_t)HW];
            float p3 = pred[base + 3 * (size_t)HW];
            loss += sl1(p0 - ttx) + sl1(p1 - tty) + sl1(p2 - ttw) + sl1(p3 - tth);

            float c0 = pred[base + 5 * (size_t)HW];
            float c1 = pred[base + 6 * (size_t)HW];
            float c2 = pred[base + 7 * (size_t)HW];
            float m  = fmaxf(c0, fmaxf(c1, c2));
            float lse = m + logf(expf(c0 - m) + expf(c1 - m) + expf(c2 - m));
            int   t   = max(wlbl[BX], 0);
            float pt  = (t == 0) ? c0 : ((t == 1) ? c1 : c2);
            loss += lse - pt;
        }
    }

    #pragma unroll
    for (int o = 16; o; o >>= 1) {
        loss += __shfl_down_sync(0xFFFFFFFFu, loss, o);
        cpos += __shfl_down_sync(0xFFFFFFFFu, cpos, o);
    }
    if (lane == 0) { rs[wid] = loss; rc[wid] = cpos; }
    __syncthreads();
    if (tid == 0) {
        float L = 0.0f; int C = 0;
        #pragma unroll
        for (int i = 0; i < 16; ++i) { L += rs[i]; C += rc[i]; }
        if (L != 0.0f) atomicAdd(&g_acc, (double)L);
        if (C)         atomicAdd(&g_numpos[b * 3 + scale], C);
    }

    unsigned* gh = g_hist + (b * 3 + scale) * PB;
    for (int i = tid; i < PB; i += 512) {
        unsigned c = sh_hist[i];
        if (c) atomicAdd(&gh[i], c);
    }
}

// ---------------------------------------------------------------------------
// Fused select + finalize, one block per task (1024 threads).
// Block->task remap puts all scale-0 (big) tasks in blocks 0..63 so the
// second wave (grid 192 > 148 SMs at 1 block/SM) holds only tiny tasks.
// Phase A: descending scan of positive-key histogram -> top-12 threshold + kk
//          (fallback flag if k exceeds all positive keys — exact, rare).
// Phase B: one pass over keys: sum softplus above threshold, compact ties.
// Phase C: generic refine: [top12 if fallback] -> mid12 -> low8.
// Last-finished block writes the output and resets accumulators.
// ---------------------------------------------------------------------------
__global__ __launch_bounds__(1024) void k_select(float* out) {
    __shared__ unsigned s_tie[SH_CAP];
    __shared__ unsigned h2[HB];
    __shared__ unsigned h3[256];
    __shared__ int      s_tiecnt;
    __shared__ int      sT, sKK, sSum, sT2, sKK2, sT3, sKK3;
    __shared__ float    rs[32];

    // wave-friendly remap: blocks 0..63 -> scale 0, 64..127 -> 1, 128..191 -> 2
    const int s = blockIdx.x >> 6;
    const int b = blockIdx.x & 63;
    const int task = b * 3 + s;
    const int N   = (s == 0) ? 49152 : ((s == 1) ? 12288 : 3072);
    const int off = (s == 0) ? 0     : ((s == 1) ? 49152 : 61440);
    const int tid = threadIdx.x;

    for (int i = tid; i < HB; i += 1024) h2[i] = 0;
    if (tid < 256) h3[tid] = 0;
    if (tid == 0) s_tiecnt = 0;

    int np = g_numpos[task];
    int k = 3 * max(1, np);
    if (k > N) k = N;

    // --- Phase A: plan over positive-key histogram (2 bins/thread, desc) ---
    unsigned* gh = g_hist + task * PB;
    {
        int cnt[2], tot = 0;
        #pragma unroll
        for (int i = 0; i < 2; ++i) {
            int bin = PB - 1 - (tid * 2 + i);
            cnt[i] = (int)gh[bin];
            gh[bin] = 0;                   // restore zero
            tot += cnt[i];
        }
        int excl = scan1024(tot);
        if (excl < k && excl + tot >= k) {
            int cum = excl;
            #pragma unroll
            for (int i = 0; i < 2; ++i) {
                if (cum + cnt[i] >= k) { sT = PB - 1 - (tid * 2 + i); sKK = k - cum; break; }
                cum += cnt[i];
            }
        }
        if (tid == 1023) sSum = excl + tot;   // total positive keys
    }
    if (tid == 0) g_numpos[task] = 0;         // restore zero
    __syncthreads();
    const int Sall = sSum;
    const bool fb = (k > Sall);               // threshold below +0.0 (rare)
    unsigned T0 = 0;
    int kk = 0;
    if (!fb) { T0 = (unsigned)sT + 2048u; kk = sKK; }
    else     { kk = k - Sall; }

    // --- Phase B: one pass over keys ---
    const uint4* keys4 = (const uint4*)(g_keys + (size_t)b * TOT + off);
    unsigned* obuf = g_buf + (size_t)task * MAXN;
    const int n4 = N >> 2;

    float local = 0.0f;
    for (int base4 = 0; base4 < n4; base4 += 4096) {
        uint4 v[4]; bool ok[4];
        #pragma unroll
        for (int q = 0; q < 4; ++q) {
            int i4 = base4 + tid + q * 1024;
            ok[q] = (i4 < n4);
            if (ok[q]) v[q] = keys4[i4];
        }
        #pragma unroll
        for (int q = 0; q < 4; ++q) {
            if (!ok[q]) continue;
            unsigned uu[4] = {f2u(__uint_as_float(v[q].x)), f2u(__uint_as_float(v[q].y)),
                              f2u(__uint_as_float(v[q].z)), f2u(__uint_as_float(v[q].w))};
            #pragma unroll
            for (int e = 0; e < 4; ++e) {
                unsigned u = uu[e];
                bool sum_it, tie_it;
                if (!fb) {
                    unsigned bin = u >> 20;
                    sum_it = (bin > T0);
                    tie_it = (bin == T0);
                } else {
                    sum_it = (u >= 0x80000000u);
                    tie_it = !sum_it;
                }
                if (sum_it) local += softplus0(key2f(u));
                else if (tie_it) {
                    int idx = atomicAdd(&s_tiecnt, 1);
                    if (idx < SH_CAP) s_tie[idx] = u;
                    else              obuf[idx - SH_CAP] = u;
                }
            }
        }
    }
    __syncthreads();
    const int m = s_tiecnt;

    // --- fallback level 0: select top-12 bin among tie members ---
    if (fb) {
        for (int i = tid; i < m; i += 1024) {
            unsigned u = (i < SH_CAP) ? s_tie[i] : obuf[i - SH_CAP];
            atomicAdd(&h2[u >> 20], 1u);
        }
        __syncthreads();
        {
            int c0[4], t0 = 0;
            #pragma unroll
            for (int i = 0; i < 4; ++i) {
                int bin = HB - 1 - (tid * 4 + i);
                c0[i] = (int)h2[bin];
                t0 += c0[i];
            }
            int ex = scan1024(t0);
            if (ex < kk && ex + t0 >= kk) {
                int cum = ex;
                #pragma unroll
                for (int i = 0; i < 4; ++i) {
                    if (cum + c0[i] >= kk) { sT2 = HB - 1 - (tid * 4 + i); sKK2 = kk - cum; break; }
                    cum += c0[i];
                }
            }
        }
        __syncthreads();
        T0 = (unsigned)sT2;
        kk = sKK2;
        for (int i = tid; i < HB; i += 1024) h2[i] = 0;   // re-zero for C1
        __syncthreads();
    }

    // --- Phase C1: sum tops>T0 (fb only), mid-12 histogram of top==T0 ---
    for (int i = tid; i < m; i += 1024) {
        unsigned u = (i < SH_CAP) ? s_tie[i] : obuf[i - SH_CAP];
        unsigned top = u >> 20;
        if (top > T0)       local += softplus0(key2f(u));
        else if (top == T0) atomicAdd(&h2[(u >> 8) & 0xFFFu], 1u);
    }
    __syncthreads();
    {
        int c2[4], t2 = 0;
        #pragma unroll
        for (int i = 0; i < 4; ++i) {
            int bin = HB - 1 - (tid * 4 + i);
            c2[i] = (int)h2[bin];
            t2 += c2[i];
        }
        int ex = scan1024(t2);
        if (ex < kk && ex + t2 >= kk) {
            int cum = ex;
            #pragma unroll
            for (int i = 0; i < 4; ++i) {
                if (cum + c2[i] >= kk) { sT2 = HB - 1 - (tid * 4 + i); sKK2 = kk - cum; break; }
                cum += c2[i];
            }
        }
    }
    __syncthreads();
    const unsigned T2 = (unsigned)sT2;
    const int kk2 = sKK2;

    // --- Phase C2: sum mid>T2; low-byte histogram for mid==T2 ---
    for (int i = tid; i < m; i += 1024) {
        unsigned u = (i < SH_CAP) ? s_tie[i] : obuf[i - SH_CAP];
        if ((u >> 20) != T0) continue;
        unsigned mid = (u >> 8) & 0xFFFu;
        if (mid > T2)       local += softplus0(key2f(u));
        else if (mid == T2) atomicAdd(&h3[u & 0xFFu], 1u);
    }
    __syncthreads();
    {
        int c3 = (tid < 256) ? (int)h3[255 - tid] : 0;
        int ex = scan1024(c3);
        if (tid < 256 && ex < kk2 && ex + c3 >= kk2) { sT3 = 255 - tid; sKK3 = kk2 - ex; }
    }
    __syncthreads();
    const unsigned T3 = (unsigned)sT3;
    const int kk3 = sKK3;
    const unsigned ustar = (T0 << 20) | (T2 << 8) | T3;

    // --- Phase C3: top==T0 && mid==T2 && low>T3 ---
    for (int i = tid; i < m; i += 1024) {
        unsigned u = (i < SH_CAP) ? s_tie[i] : obuf[i - SH_CAP];
        if ((u >> 20) == T0 && ((u >> 8) & 0xFFFu) == T2 && (u & 0xFFu) > T3)
            local += softplus0(key2f(u));
    }

    // block reduction (32 warps)
    #pragma unroll
    for (int o = 16; o; o >>= 1) local += __shfl_down_sync(0xFFFFFFFFu, local, o);
    const int wid = tid >> 5, lane = tid & 31;
    if (lane == 0) rs[wid] = local;
    __syncthreads();
    if (tid == 0) {
        float tot2 = 0.0f;
        #pragma unroll
        for (int i = 0; i < 32; ++i) tot2 += rs[i];
        tot2 += (float)kk3 * softplus0(key2f(ustar));
        atomicAdd(&g_acc, (double)tot2);

        // finalize: last-finished block writes the output
        __threadfence();
        unsigned d = atomicAdd(&g_done, 1u);
        if (d == NTASK - 1) {
            unsigned long long bits =
                atomicAdd((unsigned long long*)&g_acc, 0ULL);   // coherent read
            out[0] = (float)(__longlong_as_double(bits) * (1.0 / 64.0));
            atomicExch((unsigned long long*)&g_acc, 0ULL);       // reset
            atomicExch(&g_done, 0u);                             // reset
        }
    }
}

extern "C" void kernel_launch(void* const* d_in, const int* in_sizes, int n_in,
                              void* d_out, int out_size)
{
    const float* pred0 = (const float*)d_in[0];
    const float* pred1 = (const float*)d_in[2];
    const float* pred2 = (const float*)d_in[4];
    const float* gtb   = (const float*)d_in[6];
    const int*   gtl   = (const int*)d_in[7];

    dim3 ga(42, NB);
    k_assign<<<ga, 512>>>(pred0, pred1, pred2, gtb, gtl);
    k_select<<<NTASK, 1024>>>((float*)d_out);
}